// round 2
// baseline (speedup 1.0000x reference)
#include <cuda_runtime.h>
#include <cstddef>

#define LAYERS 5
#define H 128
#define BATCH 256
#define T 2048
#define BBLK 4
#define NBLOCKS (BATCH / BBLK)   // 64
#define NTHREADS 256             // thread = (j in [0,128), ks in {0,1})

__device__ __forceinline__ float fast_sigmoid(float x) {
    return 1.0f / (1.0f + __expf(-x));
}

__global__ __launch_bounds__(NTHREADS, 1)
void gru_persistent_kernel(
    const float* __restrict__ inp,   // [B,T,H]
    const float* __restrict__ W_hr, const float* __restrict__ W_xr, const float* __restrict__ b_r,
    const float* __restrict__ W_hz, const float* __restrict__ W_xz, const float* __restrict__ b_z,
    const float* __restrict__ W_hh, const float* __restrict__ W_xh, const float* __restrict__ b_h,
    float* __restrict__ out)         // [B,T,H]
{
    // Per-block state (4 batch rows, all 5 layers)
    __shared__ float h_state[LAYERS][BBLK][H];   // 10 KB
    __shared__ float xcur[BBLK][H];              // 2 KB
    __shared__ float part[2][3][BBLK][H];        // 12 KB   (ks, gate r/z/xh, b, j)
    __shared__ float parth[2][BBLK][H];          // 4 KB
    __shared__ float rh[BBLK][H];                // 2 KB    R * h_prev
    __shared__ float zbuf[BBLK][H];              // 2 KB
    __shared__ float preh[BBLK][H];              // 2 KB    x-side preact of candidate + bias
    __shared__ float bias_r[LAYERS][H];          // 2.5 KB
    __shared__ float bias_z[LAYERS][H];
    __shared__ float bias_h[LAYERS][H];

    const int tid = threadIdx.x;
    const int j   = tid & (H - 1);
    const int ks  = tid >> 7;          // which k-half this thread reduces
    const int row0 = blockIdx.x * BBLK;

    // Init hidden state to zero; stage biases into smem.
    for (int i = tid; i < LAYERS * BBLK * H; i += NTHREADS)
        (&h_state[0][0][0])[i] = 0.0f;
    for (int i = tid; i < LAYERS * H; i += NTHREADS) {
        (&bias_r[0][0])[i] = b_r[i];
        (&bias_z[0][0])[i] = b_z[i];
        (&bias_h[0][0])[i] = b_h[i];
    }
    __syncthreads();

    const int kbase = ks * (H / 2);

    for (int t = 0; t < T; ++t) {
        // Load x_t for our 4 batch rows (coalesced).
        for (int i = tid; i < BBLK * H; i += NTHREADS) {
            int b = i >> 7, k = i & (H - 1);
            xcur[b][k] = inp[((size_t)(row0 + b) * T + t) * H + k];
        }
        __syncthreads();

        const float* xin = &xcur[0][0];   // [BBLK][H] view

        #pragma unroll
        for (int l = 0; l < LAYERS; ++l) {
            const float* hp  = &h_state[l][0][0];
            const float* whr = W_hr + l * H * H;
            const float* wxr = W_xr + l * H * H;
            const float* whz = W_hz + l * H * H;
            const float* wxz = W_xz + l * H * H;
            const float* wxh = W_xh + l * H * H;
            const float* whh = W_hh + l * H * H;

            // ---- Stage A: preacts for R, Z and x-side of candidate ----
            float ar[BBLK], az[BBLK], axh[BBLK];
            #pragma unroll
            for (int b = 0; b < BBLK; ++b) { ar[b] = 0.f; az[b] = 0.f; axh[b] = 0.f; }

            #pragma unroll 4
            for (int kk = 0; kk < H / 2; ++kk) {
                const int k = kbase + kk;
                const float w1 = __ldg(whr + k * H + j);
                const float w2 = __ldg(wxr + k * H + j);
                const float w3 = __ldg(whz + k * H + j);
                const float w4 = __ldg(wxz + k * H + j);
                const float w5 = __ldg(wxh + k * H + j);
                #pragma unroll
                for (int b = 0; b < BBLK; ++b) {
                    const float hv = hp[b * H + k];
                    const float xv = xin[b * H + k];
                    ar[b]  = fmaf(hv, w1, ar[b]);
                    ar[b]  = fmaf(xv, w2, ar[b]);
                    az[b]  = fmaf(hv, w3, az[b]);
                    az[b]  = fmaf(xv, w4, az[b]);
                    axh[b] = fmaf(xv, w5, axh[b]);
                }
            }
            #pragma unroll
            for (int b = 0; b < BBLK; ++b) {
                part[ks][0][b][j] = ar[b];
                part[ks][1][b][j] = az[b];
                part[ks][2][b][j] = axh[b];
            }
            __syncthreads();

            if (ks == 0) {
                #pragma unroll
                for (int b = 0; b < BBLK; ++b) {
                    const float rp = part[0][0][b][j] + part[1][0][b][j] + bias_r[l][j];
                    const float zp = part[0][1][b][j] + part[1][1][b][j] + bias_z[l][j];
                    const float R  = fast_sigmoid(rp);
                    const float Z  = fast_sigmoid(zp);
                    rh[b][j]   = R * hp[b * H + j];
                    zbuf[b][j] = Z;
                    preh[b][j] = part[0][2][b][j] + part[1][2][b][j] + bias_h[l][j];
                }
            }
            __syncthreads();

            // ---- Stage B: (R*h) @ W_hh ----
            float ah[BBLK];
            #pragma unroll
            for (int b = 0; b < BBLK; ++b) ah[b] = 0.f;

            #pragma unroll 4
            for (int kk = 0; kk < H / 2; ++kk) {
                const int k = kbase + kk;
                const float w = __ldg(whh + k * H + j);
                #pragma unroll
                for (int b = 0; b < BBLK; ++b)
                    ah[b] = fmaf(rh[b][k], w, ah[b]);
            }
            #pragma unroll
            for (int b = 0; b < BBLK; ++b) parth[ks][b][j] = ah[b];
            __syncthreads();

            if (ks == 0) {
                #pragma unroll
                for (int b = 0; b < BBLK; ++b) {
                    const float hpre = parth[0][b][j] + parth[1][b][j] + preh[b][j];
                    const float htld = tanhf(hpre);
                    const float Z    = zbuf[b][j];
                    const float hn   = Z * htld + (1.0f - Z) * hp[b * H + j];
                    h_state[l][b][j] = hn;
                    if (l == LAYERS - 1)
                        out[((size_t)(row0 + b) * T + t) * H + j] = hn;
                }
            }
            __syncthreads();

            xin = &h_state[l][0][0];   // becomes next layer's input
        }
    }
}

extern "C" void kernel_launch(void* const* d_in, const int* in_sizes, int n_in,
                              void* d_out, int out_size) {
    (void)in_sizes; (void)n_in; (void)out_size;
    const float* inp  = (const float*)d_in[0];
    const float* W_hr = (const float*)d_in[1];
    const float* W_xr = (const float*)d_in[2];
    const float* b_r  = (const float*)d_in[3];
    const float* W_hz = (const float*)d_in[4];
    const float* W_xz = (const float*)d_in[5];
    const float* b_z  = (const float*)d_in[6];
    const float* W_hh = (const float*)d_in[7];
    const float* W_xh = (const float*)d_in[8];
    const float* b_h  = (const float*)d_in[9];
    float* out = (float*)d_out;

    gru_persistent_kernel<<<NBLOCKS, NTHREADS>>>(
        inp, W_hr, W_xr, b_r, W_hz, W_xz, b_z, W_hh, W_xh, b_h, out);
}

// round 3
// speedup vs baseline: 2.2737x; 2.2737x over previous
#include <cuda_runtime.h>
#include <cstddef>

#define LAYERS 5
#define H 128
#define BATCH 256
#define T 2048
#define BBLK 4
#define NBLOCKS 64
#define NTHREADS 256
#define KSLICES 8
#define KPER 16

typedef unsigned long long ull;

__device__ __forceinline__ ull pack2(float lo, float hi) {
    ull r; asm("mov.b64 %0,{%1,%2};" : "=l"(r) : "f"(lo), "f"(hi)); return r;
}
__device__ __forceinline__ void fma2(ull& acc, ull a, ull b) {
    asm("fma.rn.f32x2 %0,%1,%2,%0;" : "+l"(acc) : "l"(a), "l"(b));
}
__device__ __forceinline__ float2 unpack2(ull v) {
    float lo, hi; asm("mov.b64 {%0,%1},%2;" : "=f"(lo), "=f"(hi) : "l"(v));
    return make_float2(lo, hi);
}
__device__ __forceinline__ float fast_sigmoid(float x) {
    return 1.0f / (1.0f + __expf(-x));
}

struct Smem {
    float h_state[LAYERS][BBLK][H];     // 10 KB
    float xcur[2][BBLK][H];             // 4 KB (double-buffered input)
    float partA[KSLICES][3][BBLK][H];   // 48 KB
    float partB[KSLICES][BBLK][H];      // 16 KB
    float rh[BBLK][H];
    float zbuf[BBLK][H];
    float preh[BBLK][H];
    float bias_r[LAYERS][H];
    float bias_z[LAYERS][H];
    float bias_h[LAYERS][H];
};

__global__ __launch_bounds__(NTHREADS, 1)
void gru_persistent_kernel(
    const float* __restrict__ inp,
    const float* __restrict__ W_hr, const float* __restrict__ W_xr, const float* __restrict__ b_r,
    const float* __restrict__ W_hz, const float* __restrict__ W_xz, const float* __restrict__ b_z,
    const float* __restrict__ W_hh, const float* __restrict__ W_xh, const float* __restrict__ b_h,
    float* __restrict__ out)
{
    extern __shared__ char smem_raw[];
    Smem& sm = *reinterpret_cast<Smem*>(smem_raw);

    const int tid  = threadIdx.x;
    const int j4   = tid & 31;          // 4 output columns: j0..j0+3
    const int j0   = j4 << 2;
    const int ks   = tid >> 5;          // k-slice (warp id), 8 slices of 16
    const int k0   = ks * KPER;
    const int row0 = blockIdx.x * BBLK;

    // ---- init ----
    for (int i = tid; i < LAYERS * BBLK * H; i += NTHREADS)
        (&sm.h_state[0][0][0])[i] = 0.0f;
    for (int i = tid; i < LAYERS * H; i += NTHREADS) {
        (&sm.bias_r[0][0])[i] = b_r[i];
        (&sm.bias_z[0][0])[i] = b_z[i];
        (&sm.bias_h[0][0])[i] = b_h[i];
    }
    // preload x_0
    {
        int b = tid >> 7, k = tid & 127;
        sm.xcur[0][b][k]     = inp[((size_t)(row0 + b) * T + 0) * H + k];
        sm.xcur[0][b + 2][k] = inp[((size_t)(row0 + b + 2) * T + 0) * H + k];
    }
    __syncthreads();

    for (int t = 0; t < T; ++t) {
        const int cur = t & 1, nxt = cur ^ 1;

        // prefetch x_{t+1} into registers (hidden under layer compute)
        float p0 = 0.f, p1 = 0.f;
        const bool havepre = (t + 1 < T);
        const int pb = tid >> 7, pk = tid & 127;
        if (havepre) {
            p0 = inp[((size_t)(row0 + pb) * T + (t + 1)) * H + pk];
            p1 = inp[((size_t)(row0 + pb + 2) * T + (t + 1)) * H + pk];
        }

        const float(*xin)[H] = sm.xcur[cur];

        #pragma unroll
        for (int l = 0; l < LAYERS; ++l) {
            const float(*hp)[H] = sm.h_state[l];
            const float* whr = W_hr + l * H * H;
            const float* wxr = W_xr + l * H * H;
            const float* whz = W_hz + l * H * H;
            const float* wxz = W_xz + l * H * H;
            const float* wxh = W_xh + l * H * H;
            const float* whh = W_hh + l * H * H;

            // ======== Stage A: h@Whr + x@Wxr, h@Whz + x@Wxz, x@Wxh ========
            ull ar[2][BBLK], az[2][BBLK], ax[2][BBLK];
            #pragma unroll
            for (int b = 0; b < BBLK; ++b) {
                ar[0][b] = ar[1][b] = 0ull;
                az[0][b] = az[1][b] = 0ull;
                ax[0][b] = ax[1][b] = 0ull;
            }

            #pragma unroll
            for (int kk4 = 0; kk4 < KPER / 4; ++kk4) {
                const int kb = k0 + kk4 * 4;
                float4 h4[BBLK], x4[BBLK];
                #pragma unroll
                for (int b = 0; b < BBLK; ++b) {
                    h4[b] = *reinterpret_cast<const float4*>(&hp[b][kb]);
                    x4[b] = *reinterpret_cast<const float4*>(&xin[b][kb]);
                }
                #pragma unroll
                for (int s = 0; s < 4; ++s) {
                    const int k = kb + s;
                    const float4 w1 = __ldg(reinterpret_cast<const float4*>(whr + k * H + j0));
                    const float4 w2 = __ldg(reinterpret_cast<const float4*>(wxr + k * H + j0));
                    const float4 w3 = __ldg(reinterpret_cast<const float4*>(whz + k * H + j0));
                    const float4 w4 = __ldg(reinterpret_cast<const float4*>(wxz + k * H + j0));
                    const float4 w5 = __ldg(reinterpret_cast<const float4*>(wxh + k * H + j0));
                    const ull w1l = pack2(w1.x, w1.y), w1h = pack2(w1.z, w1.w);
                    const ull w2l = pack2(w2.x, w2.y), w2h = pack2(w2.z, w2.w);
                    const ull w3l = pack2(w3.x, w3.y), w3h = pack2(w3.z, w3.w);
                    const ull w4l = pack2(w4.x, w4.y), w4h = pack2(w4.z, w4.w);
                    const ull w5l = pack2(w5.x, w5.y), w5h = pack2(w5.z, w5.w);
                    #pragma unroll
                    for (int b = 0; b < BBLK; ++b) {
                        const float hv = (s == 0) ? h4[b].x : (s == 1) ? h4[b].y : (s == 2) ? h4[b].z : h4[b].w;
                        const float xv = (s == 0) ? x4[b].x : (s == 1) ? x4[b].y : (s == 2) ? x4[b].z : x4[b].w;
                        const ull h2 = pack2(hv, hv);
                        const ull x2 = pack2(xv, xv);
                        fma2(ar[0][b], w1l, h2); fma2(ar[1][b], w1h, h2);
                        fma2(ar[0][b], w2l, x2); fma2(ar[1][b], w2h, x2);
                        fma2(az[0][b], w3l, h2); fma2(az[1][b], w3h, h2);
                        fma2(az[0][b], w4l, x2); fma2(az[1][b], w4h, x2);
                        fma2(ax[0][b], w5l, x2); fma2(ax[1][b], w5h, x2);
                    }
                }
            }
            #pragma unroll
            for (int b = 0; b < BBLK; ++b) {
                float2 r0 = unpack2(ar[0][b]), r1 = unpack2(ar[1][b]);
                float2 z0 = unpack2(az[0][b]), z1 = unpack2(az[1][b]);
                float2 x0 = unpack2(ax[0][b]), x1 = unpack2(ax[1][b]);
                *reinterpret_cast<float4*>(&sm.partA[ks][0][b][j0]) = make_float4(r0.x, r0.y, r1.x, r1.y);
                *reinterpret_cast<float4*>(&sm.partA[ks][1][b][j0]) = make_float4(z0.x, z0.y, z1.x, z1.y);
                *reinterpret_cast<float4*>(&sm.partA[ks][2][b][j0]) = make_float4(x0.x, x0.y, x1.x, x1.y);
            }
            __syncthreads();

            // ---- Combine A: reduce 8 slices, activations ----
            for (int i = tid; i < 3 * BBLK * H; i += NTHREADS) {
                const int g = i >> 9;
                const int r = i & 511;
                const int b = r >> 7;
                const int j = r & 127;
                float ssum = 0.f;
                #pragma unroll
                for (int ss = 0; ss < KSLICES; ++ss) ssum += sm.partA[ss][g][b][j];
                if (g == 0) {
                    const float R = fast_sigmoid(ssum + sm.bias_r[l][j]);
                    sm.rh[b][j] = R * sm.h_state[l][b][j];
                } else if (g == 1) {
                    sm.zbuf[b][j] = fast_sigmoid(ssum + sm.bias_z[l][j]);
                } else {
                    sm.preh[b][j] = ssum + sm.bias_h[l][j];
                }
            }
            __syncthreads();

            // ======== Stage B: (R*h) @ W_hh ========
            ull bh[2][BBLK];
            #pragma unroll
            for (int b = 0; b < BBLK; ++b) { bh[0][b] = 0ull; bh[1][b] = 0ull; }

            #pragma unroll
            for (int kk4 = 0; kk4 < KPER / 4; ++kk4) {
                const int kb = k0 + kk4 * 4;
                float4 r4[BBLK];
                #pragma unroll
                for (int b = 0; b < BBLK; ++b)
                    r4[b] = *reinterpret_cast<const float4*>(&sm.rh[b][kb]);
                #pragma unroll
                for (int s = 0; s < 4; ++s) {
                    const int k = kb + s;
                    const float4 w = __ldg(reinterpret_cast<const float4*>(whh + k * H + j0));
                    const ull wl = pack2(w.x, w.y), wh = pack2(w.z, w.w);
                    #pragma unroll
                    for (int b = 0; b < BBLK; ++b) {
                        const float rv = (s == 0) ? r4[b].x : (s == 1) ? r4[b].y : (s == 2) ? r4[b].z : r4[b].w;
                        const ull r2 = pack2(rv, rv);
                        fma2(bh[0][b], wl, r2);
                        fma2(bh[1][b], wh, r2);
                    }
                }
            }
            #pragma unroll
            for (int b = 0; b < BBLK; ++b) {
                float2 b0 = unpack2(bh[0][b]), b1 = unpack2(bh[1][b]);
                *reinterpret_cast<float4*>(&sm.partB[ks][b][j0]) = make_float4(b0.x, b0.y, b1.x, b1.y);
            }
            __syncthreads();

            // ---- Combine B: tanh + blend, write new h ----
            for (int i = tid; i < BBLK * H; i += NTHREADS) {
                const int b = i >> 7;
                const int j = i & 127;
                float ssum = 0.f;
                #pragma unroll
                for (int ss = 0; ss < KSLICES; ++ss) ssum += sm.partB[ss][b][j];
                const float hpre = ssum + sm.preh[b][j];
                const float htld = tanhf(hpre);
                const float Z    = sm.zbuf[b][j];
                const float hn   = Z * htld + (1.0f - Z) * sm.h_state[l][b][j];
                sm.h_state[l][b][j] = hn;
                if (l == LAYERS - 1)
                    out[((size_t)(row0 + b) * T + t) * H + j] = hn;
            }
            __syncthreads();

            xin = sm.h_state[l];
        }

        // stash prefetched x_{t+1}
        if (havepre) {
            sm.xcur[nxt][pb][pk]     = p0;
            sm.xcur[nxt][pb + 2][pk] = p1;
        }
        __syncthreads();
    }
}

extern "C" void kernel_launch(void* const* d_in, const int* in_sizes, int n_in,
                              void* d_out, int out_size) {
    (void)in_sizes; (void)n_in; (void)out_size;
    const float* inp  = (const float*)d_in[0];
    const float* W_hr = (const float*)d_in[1];
    const float* W_xr = (const float*)d_in[2];
    const float* b_r  = (const float*)d_in[3];
    const float* W_hz = (const float*)d_in[4];
    const float* W_xz = (const float*)d_in[5];
    const float* b_z  = (const float*)d_in[6];
    const float* W_hh = (const float*)d_in[7];
    const float* W_xh = (const float*)d_in[8];
    const float* b_h  = (const float*)d_in[9];
    float* out = (float*)d_out;

    cudaFuncSetAttribute(gru_persistent_kernel,
                         cudaFuncAttributeMaxDynamicSharedMemorySize,
                         (int)sizeof(Smem));
    gru_persistent_kernel<<<NBLOCKS, NTHREADS, sizeof(Smem)>>>(
        inp, W_hr, W_xr, b_r, W_hz, W_xz, b_z, W_hh, W_xh, b_h, out);
}